// round 3
// baseline (speedup 1.0000x reference)
#include <cuda_runtime.h>
#include <cuda_fp16.h>
#include <mma.h>
#include <cstdint>

using namespace nvcuda;

#define DD  1024
#define NB  64
#define NKK 512
#define MROWS (NB * NKK)          // 32768 flattened z-rows

// ---------------- device scratch (no allocs allowed) ----------------
__device__ __half g_wzT[DD * DD];            // w_z transposed fp16: [e][d]
__device__ __half g_xh[(size_t)MROWS * DD];  // z in fp16, batch-flattened
__device__ float  g_c[NB * DD];              // c[b,e] = u[b] . w_u[:,e] (fp32 exact)
__device__ float  g_qp[4 * MROWS];           // partial q per n-tile

// ---------------- helpers ----------------
static __device__ __forceinline__ uint32_t smem_u32(const void* p) {
    uint32_t a;
    asm("{ .reg .u64 t; cvta.to.shared.u64 t, %1; cvt.u32.u64 %0, t; }" : "=r"(a) : "l"(p));
    return a;
}
#define CP16(dst, src) \
    asm volatile("cp.async.cg.shared.global [%0], [%1], 16;" :: "r"(dst), "l"(src))
#define CP_COMMIT() asm volatile("cp.async.commit_group;" ::: "memory")
#define CP_WAIT(n)  asm volatile("cp.async.wait_group %0;" :: "n"(n) : "memory")

// exact identity tanh(x) = 1 - 2/(e^{2x}+1), via ex2.approx + rcp.approx (~1e-6)
static __device__ __forceinline__ float fast_tanh(float x) {
    float e;
    asm("ex2.approx.f32 %0, %1;" : "=f"(e) : "f"(x * 2.885390081777927f)); // 2*log2(e)
    float r;
    asm("rcp.approx.f32 %0, %1;" : "=f"(r) : "f"(e + 1.0f));
    return fmaf(-2.0f, r, 1.0f);
}

// ---------------- SMEM layout of the main kernel ----------------
static constexpr int LDH      = 72;                    // padded halves per row (144B)
static constexpr int SA_BYTES = 128 * LDH * 2;         // 18432
static constexpr int SB_BYTES = 256 * LDH * 2;         // 36864
static constexpr int OFF_SA   = 0;
static constexpr int OFF_SB   = 2 * SA_BYTES;          // 36864
static constexpr int OFF_C    = OFF_SB + 2 * SB_BYTES; // 110592
static constexpr int OFF_BI   = OFF_C + 1024;
static constexpr int OFF_QB   = OFF_BI + 1024;
static constexpr int SMEM_MAIN = OFF_QB + 2048;        // 114688

// ---------------- kernel 0a: z -> fp16 (batch-flattened, skip u row) ----------------
__global__ void __launch_bounds__(256) xhalf_kernel(const float* __restrict__ x) {
    size_t g = (size_t)blockIdx.x * 256 + threadIdx.x;   // float4 index
#pragma unroll
    for (int j = 0; j < 4; j++, g += 2097152) {
        size_t m  = g >> 8;            // row in [0, 32768)
        int    c4 = (int)(g & 255);
        size_t b  = m >> 9, k = m & 511;
        float4 v = __ldg(reinterpret_cast<const float4*>(x + ((b * 513 + 1 + k) << 10)) + c4);
        __half2 h0 = __floats2half2_rn(v.x, v.y);
        __half2 h1 = __floats2half2_rn(v.z, v.w);
        uint32_t* dst = reinterpret_cast<uint32_t*>(g_xh + (m << 10)) + c4 * 2;
        dst[0] = *reinterpret_cast<uint32_t*>(&h0);
        dst[1] = *reinterpret_cast<uint32_t*>(&h1);
    }
}

// ---------------- kernel 0b: transpose + fp16 convert of w_z ----------------
__global__ void transpose_kernel(const float* __restrict__ W) {
    __shared__ float tile[32][33];
    const int d0 = blockIdx.x * 32, e0 = blockIdx.y * 32;
    const int tx = threadIdx.x, ty = threadIdx.y;
#pragma unroll
    for (int i = 0; i < 32; i += 8)
        tile[ty + i][tx] = W[(size_t)(d0 + ty + i) * DD + e0 + tx];
    __syncthreads();
#pragma unroll
    for (int i = 0; i < 32; i += 8)
        g_wzT[(size_t)(e0 + ty + i) * DD + d0 + tx] = __float2half(tile[tx][ty + i]);
}

// ---------------- kernel 0c: c[b,e] = u[b] . w_u[:,e] (fp32 exact) ----------------
__global__ void __launch_bounds__(256) cvec_kernel(const float* __restrict__ x,
                                                   const float* __restrict__ W) {
    __shared__ float us[4][DD];
    const int e  = blockIdx.x * 256 + threadIdx.x;
    const int b0 = blockIdx.y * 4;
    for (int i = threadIdx.x; i < 4 * DD; i += 256) {
        int j = i >> 10, d = i & (DD - 1);
        us[j][d] = x[(size_t)(b0 + j) * 513 * DD + d];
    }
    __syncthreads();
    const float* wu = W + (size_t)DD * DD;
    float a0 = 0, a1 = 0, a2 = 0, a3 = 0;
#pragma unroll 4
    for (int d = 0; d < DD; d++) {
        float w = __ldg(wu + (size_t)d * DD + e);
        a0 = fmaf(us[0][d], w, a0);
        a1 = fmaf(us[1][d], w, a1);
        a2 = fmaf(us[2][d], w, a2);
        a3 = fmaf(us[3][d], w, a3);
    }
    g_c[(b0 + 0) * DD + e] = a0;
    g_c[(b0 + 1) * DD + e] = a1;
    g_c[(b0 + 2) * DD + e] = a2;
    g_c[(b0 + 3) * DD + e] = a3;
}

// ---------------- kernel 1: fused GEMM(HMMA) + tanh + bias-dot ----------------
// grid = 1024: mtile(256) x ntile(4). CTA 512 thr: tile M=128 x N=256, K=1024.
__global__ void __launch_bounds__(512, 1) main_kernel(const float* __restrict__ bias) {
    extern __shared__ char smem[];
    const uint32_t sb = smem_u32(smem);
    const int tid = threadIdx.x;
    const int w   = tid >> 5, lane = tid & 31;
    const int wm  = w >> 2,  wn   = w & 3;
    const int nt    = blockIdx.x & 3;
    const int mtile = blockIdx.x >> 2;
    const int m0    = mtile * 128;
    const int b     = m0 >> 9;

    float* c_sm  = reinterpret_cast<float*>(smem + OFF_C);
    float* bi_sm = reinterpret_cast<float*>(smem + OFF_BI);
    if (tid < 256) {
        c_sm[tid]  = g_c[b * DD + nt * 256 + tid];
        bi_sm[tid] = bias[nt * 256 + tid];
    }

    const __half* Ab = g_xh  + (size_t)m0 * DD;
    const __half* Bb = g_wzT + (size_t)nt * 256 * DD;

    // per K-chunk (64 halves = 128 B/row = 8 x 16B segments per row)
    auto issue = [&](int kc, int buf) {
#pragma unroll
        for (int j = 0; j < 2; j++) {   // A: 128 rows x 8 segs = 1024
            int i = tid + j * 512;
            int row = i >> 3, v = i & 7;
            uint32_t dst = sb + OFF_SA + buf * SA_BYTES + row * 144 + v * 16;
            CP16(dst, Ab + (size_t)row * DD + kc * 64 + v * 8);
        }
#pragma unroll
        for (int j = 0; j < 4; j++) {   // B: 256 rows x 8 segs = 2048
            int i = tid + j * 512;
            int row = i >> 3, v = i & 7;
            uint32_t dst = sb + OFF_SB + buf * SB_BYTES + row * 144 + v * 16;
            CP16(dst, Bb + (size_t)row * DD + kc * 64 + v * 8);
        }
        CP_COMMIT();
    };

    wmma::fragment<wmma::accumulator, 16, 16, 16, float> acc[2][4];
#pragma unroll
    for (int mi = 0; mi < 2; mi++)
#pragma unroll
        for (int ni = 0; ni < 4; ni++)
            wmma::fill_fragment(acc[mi][ni], 0.0f);

    issue(0, 0);
    for (int kc = 0; kc < 16; kc++) {
        const int cur = kc & 1;
        if (kc < 15) { issue(kc + 1, cur ^ 1); CP_WAIT(1); }
        else         { CP_WAIT(0); }
        __syncthreads();

        const __half* sA = reinterpret_cast<const __half*>(smem + OFF_SA + cur * SA_BYTES);
        const __half* sB = reinterpret_cast<const __half*>(smem + OFF_SB + cur * SB_BYTES);
#pragma unroll
        for (int ks = 0; ks < 4; ks++) {
            wmma::fragment<wmma::matrix_a, 16, 16, 16, __half, wmma::row_major> af[2];
            wmma::load_matrix_sync(af[0], sA + (wm * 32 +  0) * LDH + ks * 16, LDH);
            wmma::load_matrix_sync(af[1], sA + (wm * 32 + 16) * LDH + ks * 16, LDH);
#pragma unroll
            for (int ni = 0; ni < 4; ni++) {
                wmma::fragment<wmma::matrix_b, 16, 16, 16, __half, wmma::col_major> bf;
                wmma::load_matrix_sync(bf, sB + (wn * 64 + ni * 16) * LDH + ks * 16, LDH);
                wmma::mma_sync(acc[0][ni], af[0], bf, acc[0][ni]);
                wmma::mma_sync(acc[1][ni], af[1], bf, acc[1][ni]);
            }
        }
        __syncthreads();
    }

    // ---- epilogue: acc -> +c -> tanh -> *bias -> per-row partial q ----
    float* scr = reinterpret_cast<float*>(smem) + w * 1152;   // 32 x 36 per warp
    float q = 0.0f;
#pragma unroll
    for (int h = 0; h < 2; h++) {
#pragma unroll
        for (int mi = 0; mi < 2; mi++)
#pragma unroll
            for (int n2 = 0; n2 < 2; n2++)
                wmma::store_matrix_sync(scr + mi * 16 * 36 + n2 * 16,
                                        acc[mi][h * 2 + n2], 36, wmma::mem_row_major);
        __syncwarp();
        float p = 0.0f;
#pragma unroll
        for (int j = 0; j < 32; j++) {
            const int col = wn * 64 + h * 32 + j;
            float s = scr[lane * 36 + j] + c_sm[col];
            p = fmaf(fast_tanh(s), bi_sm[col], p);
        }
        q += p;
        __syncwarp();
    }
    float* qb = reinterpret_cast<float*>(smem + OFF_QB);
    qb[wn * 128 + wm * 32 + lane] = q;
    __syncthreads();
    if (tid < 128) {
        float s = qb[tid] + qb[128 + tid] + qb[256 + tid] + qb[384 + tid];
        g_qp[(size_t)nt * MROWS + m0 + tid] = s;
    }
}

// ---------------- kernel 2: softmax over k=512 per batch ----------------
__global__ void __launch_bounds__(512) softmax_kernel(float* __restrict__ out) {
    __shared__ float sred[16];
    __shared__ float sbc;
    const int b = blockIdx.x, t = threadIdx.x;
    const int wid = t >> 5, lid = t & 31;
    const int idx = b * NKK + t;
    float v = g_qp[idx] + g_qp[MROWS + idx] + g_qp[2 * MROWS + idx] + g_qp[3 * MROWS + idx];

    float m = v;
#pragma unroll
    for (int o = 16; o; o >>= 1) m = fmaxf(m, __shfl_xor_sync(0xffffffffu, m, o));
    if (lid == 0) sred[wid] = m;
    __syncthreads();
    if (wid == 0) {
        float mm = (lid < 16) ? sred[lid] : -1e30f;
#pragma unroll
        for (int o = 16; o; o >>= 1) mm = fmaxf(mm, __shfl_xor_sync(0xffffffffu, mm, o));
        if (lid == 0) sbc = mm;
    }
    __syncthreads();
    const float M = sbc;
    float e;
    asm("ex2.approx.f32 %0, %1;" : "=f"(e) : "f"((v - M) * 1.4426950408889634f));
    float s = e;
#pragma unroll
    for (int o = 16; o; o >>= 1) s += __shfl_xor_sync(0xffffffffu, s, o);
    __syncthreads();
    if (lid == 0) sred[wid] = s;
    __syncthreads();
    if (wid == 0) {
        float ss = (lid < 16) ? sred[lid] : 0.f;
#pragma unroll
        for (int o = 16; o; o >>= 1) ss += __shfl_xor_sync(0xffffffffu, ss, o);
        if (lid == 0) sbc = ss;
    }
    __syncthreads();
    out[idx] = e / sbc;
}

// ---------------- launch ----------------
extern "C" void kernel_launch(void* const* d_in, const int* in_sizes, int n_in,
                              void* d_out, int out_size) {
    const float* x    = (const float*)d_in[0];
    const float* W    = (const float*)d_in[1];
    const float* bias = (const float*)d_in[2];
    float* out = (float*)d_out;

    cudaFuncSetAttribute(main_kernel, cudaFuncAttributeMaxDynamicSharedMemorySize, SMEM_MAIN);

    xhalf_kernel<<<8192, 256>>>(x);
    transpose_kernel<<<dim3(32, 32), dim3(32, 8)>>>(W);
    cvec_kernel<<<dim3(4, 16), 256>>>(x, W);
    main_kernel<<<1024, 512, SMEM_MAIN>>>(bias);
    softmax_kernel<<<64, 512>>>(out);
}